// round 5
// baseline (speedup 1.0000x reference)
#include <cuda_runtime.h>
#include <cuda_fp16.h>

// GaussianLayer: 2D Gaussian "same" conv (25x25, center tap zeroed) over
// src (4,512,512,21) NHWC fp32.  dst = g_y * (g_x * src) - src.
// Round 5: round-4 design with the out_s smem offset padded to 16B
// (fixes the misaligned uint4 shared loads in the writeback).

#define BATCH 4
#define HH    512
#define WW    512
#define CC    21
#define RR    12
#define TAPS  25
#define ROWF  (WW * CC)          /* 10752 floats per (b,y) row */
#define IMGF  (HH * ROWF)
#define TOTALF (BATCH * IMGF)    /* 22,020,096 */

#define S_ROW 538                /* smem transposed row stride (even, padded) */
#define OUT_S_OFF 45200          /* CC*S_ROW*4 = 45192, rounded up to 16B     */

typedef unsigned long long u64;

// fp16 scratch, 16B-aligned for uint4 stores: TOTALF/8 uint4s = 44 MB
__device__ uint4 g_tmp4[TOTALF / 8];

__device__ __forceinline__ u64 pack2(float lo, float hi) {
    u64 r; asm("mov.b64 %0, {%1, %2};" : "=l"(r) : "f"(lo), "f"(hi)); return r;
}
__device__ __forceinline__ void fma2(u64& d, u64 a, u64 b) {
    asm("fma.rn.f32x2 %0, %1, %2, %0;" : "+l"(d) : "l"(a), "l"(b));
}
__device__ __forceinline__ float2 unpack2(u64 v) {
    float2 f; asm("mov.b64 {%0, %1}, %2;" : "=f"(f.x), "=f"(f.y) : "l"(v)); return f;
}

// 13 symmetric 1D weights from row RR of the 2D kernel; center weight = 1
// (the zeroed 2D center tap is handled by subtracting src at the end).
__device__ __forceinline__ void load_weights(const float* __restrict__ k, u64* W2) {
#pragma unroll
    for (int j = 0; j < 12; ++j) {
        float w = __ldg(k + RR * TAPS + j);
        W2[j] = pack2(w, w);
    }
    W2[12] = pack2(1.0f, 1.0f);
}

// ---------------- Pass 1: horizontal, one block per (b,y) row --------------
__global__ void __launch_bounds__(256) pass_h_kernel(const float* __restrict__ src,
                                                     const float* __restrict__ k) {
    extern __shared__ char sm[];
    float*  row_t = (float*)sm;                          // [CC][S_ROW]
    __half* out_s = (__half*)(sm + OUT_S_OFF);           // [ROWF] flat [x*21+c]

    const int tid = threadIdx.x;
    const int row = blockIdx.x;                          // b*HH + y
    const float* rp = src + (size_t)row * ROWF;

    u64 W2[13];
    load_weights(k, W2);

    // Zero halo borders: stored index ix in [0,11] and [524,537] per channel.
    for (int t = tid; t < CC * 26; t += 256) {
        int c = t / 26, j = t - c * 26;
        int ix = (j < 12) ? j : (524 + (j - 12));
        row_t[c * S_ROW + ix] = 0.0f;
    }

    // Coalesced load of the whole row + transpose into smem: row_t[c][x+12].
    for (int i = 0; i < 11; ++i) {
        int f4 = i * 256 + tid;
        if (f4 < ROWF / 4) {
            float4 v = *(const float4*)(rp + 4 * f4);
            int f = 4 * f4;
            float vv[4] = {v.x, v.y, v.z, v.w};
#pragma unroll
            for (int s = 0; s < 4; ++s) {
                int ff = f + s;
                int x = ff / CC;
                int c = ff - x * CC;
                row_t[c * S_ROW + x + 12] = vv[s];
            }
        }
    }
    __syncthreads();

    // Compute: 1344 units, each = (channel c, 8 consecutive x outputs).
    for (int i = 0; i < 6; ++i) {
        int u = i * 256 + tid;
        if (u < CC * 64) {
            int c  = u >> 6;
            int xq = u & 63;
            int x0 = xq * 8;
            const float* base = row_t + c * S_ROW + x0;   // = v[0] (x0-12 logical)

            u64 E[16];                                    // (v[2j], v[2j+1])
#pragma unroll
            for (int j = 0; j < 16; ++j)
                E[j] = *(const u64*)(base + 2 * j);

            u64 O[15];                                    // (v[2j+1], v[2j+2])
#pragma unroll
            for (int j = 0; j < 15; ++j) {
                float2 a = unpack2(E[j]);
                float2 b = unpack2(E[j + 1]);
                O[j] = pack2(a.y, b.x);
            }

            u64 A[4] = {0ull, 0ull, 0ull, 0ull};
#pragma unroll
            for (int j = 0; j < 13; ++j) {                // even taps n = 2j
                int n = 2 * j;
                u64 w = W2[n <= RR ? n : 24 - n];
#pragma unroll
                for (int m = 0; m < 4; ++m) fma2(A[m], w, E[j + m]);
            }
#pragma unroll
            for (int j = 0; j < 12; ++j) {                // odd taps n = 2j+1
                int n = 2 * j + 1;
                u64 w = W2[n <= RR ? n : 24 - n];
#pragma unroll
                for (int m = 0; m < 4; ++m) fma2(A[m], w, O[j + m]);
            }

#pragma unroll
            for (int m = 0; m < 4; ++m) {
                float2 o = unpack2(A[m]);
                out_s[(x0 + 2 * m)     * CC + c] = __float2half_rn(o.x);
                out_s[(x0 + 2 * m + 1) * CC + c] = __float2half_rn(o.y);
            }
        }
    }
    __syncthreads();

    // Coalesced fp16 writeback: 1344 uint4 per row.
    uint4* op = g_tmp4 + (size_t)row * (ROWF / 8);
    const uint4* os = (const uint4*)out_s;
    for (int i = 0; i < 6; ++i) {
        int u = i * 256 + tid;
        if (u < ROWF / 8) op[u] = os[u];
    }
}

// ---------------- Pass 2: vertical + subtract src (unchanged) --------------
__global__ void __launch_bounds__(256) pass_v_kernel(const float* __restrict__ src,
                                                     const float* __restrict__ k,
                                                     float* __restrict__ dst) {
    const int PAIRS = ROWF / 2;                     // 5376 pairs per row
    const int PER_B = (HH / 8) * PAIRS;             // 344,064 threads per batch
    int tid = blockIdx.x * 256 + threadIdx.x;

    int b   = tid / PER_B;
    int rem = tid - b * PER_B;
    int yg  = rem / PAIRS;
    int fp  = rem - yg * PAIRS;
    int y0  = yg * 8;

    size_t off = (size_t)b * IMGF + 2 * (size_t)fp;
    const __half* tp = (const __half*)g_tmp4 + off;
    const float*  sp = src + off;
    float*        dp = dst + off;

    u64 W2[13];
    load_weights(k, W2);

    __half2 v[32];
    if (y0 >= RR && y0 + 19 < HH) {
#pragma unroll
        for (int s = 0; s < 32; ++s)
            v[s] = *(const __half2*)(tp + (size_t)(y0 - RR + s) * ROWF);
    } else {
        const __half2 z = __float2half2_rn(0.0f);
#pragma unroll
        for (int s = 0; s < 32; ++s) {
            int yin = y0 - RR + s;
            v[s] = (yin >= 0 && yin < HH)
                       ? *(const __half2*)(tp + (size_t)yin * ROWF)
                       : z;
        }
    }

    u64 A[8] = {0ull, 0ull, 0ull, 0ull, 0ull, 0ull, 0ull, 0ull};
#pragma unroll
    for (int s = 0; s < 32; ++s) {
        float2 f = __half22float2(v[s]);
        u64 P = pack2(f.x, f.y);
#pragma unroll
        for (int m = 0; m < 8; ++m) {
            int n = s - m;
            if (n >= 0 && n < TAPS)
                fma2(A[m], W2[n <= RR ? n : 24 - n], P);
        }
    }

#pragma unroll
    for (int m = 0; m < 8; ++m) {
        float2 o  = unpack2(A[m]);
        float2 s2 = *(const float2*)(sp + (size_t)(y0 + m) * ROWF);
        float2 r;
        r.x = o.x - s2.x;
        r.y = o.y - s2.y;
        *(float2*)(dp + (size_t)(y0 + m) * ROWF) = r;
    }
}

extern "C" void kernel_launch(void* const* d_in, const int* in_sizes, int n_in,
                              void* d_out, int out_size) {
    const float* src = (const float*)d_in[0];
    const float* k   = (const float*)d_in[1];
    float*       dst = (float*)d_out;

    const int smem_h = OUT_S_OFF + ROWF * 2;              // 66,704 B
    cudaFuncSetAttribute(pass_h_kernel,
                         cudaFuncAttributeMaxDynamicSharedMemorySize, smem_h);

    pass_h_kernel<<<BATCH * HH, 256, smem_h>>>(src, k);

    int nthreads_v = BATCH * (HH / 8) * (ROWF / 2);       // 1,376,256
    pass_v_kernel<<<nthreads_v / 256, 256>>>(src, k, dst);
}

// round 6
// speedup vs baseline: 1.6217x; 1.6217x over previous
#include <cuda_runtime.h>
#include <cuda_fp16.h>

// GaussianLayer: 2D Gaussian "same" conv (25x25, center tap zeroed) over
// src (4,512,512,21) NHWC fp32.  dst = g_y * (g_x * src) - src.
// Round 6: round-3 structure (register-window gather via L1), pass_h widened
// to 16 x-outputs/thread (window 40): LDG/output 4->2.5.  pass_v unchanged.

#define BATCH 4
#define HH    512
#define WW    512
#define CC    21
#define RR    12
#define TAPS  25
#define ROWF  (WW * CC)          /* 10752 floats per (b,y) row */
#define IMGF  (HH * ROWF)
#define TOTALF (BATCH * IMGF)    /* 22,020,096 */

typedef unsigned long long u64;

__device__ __half g_tmp[TOTALF];   // 44 MB fp16 scratch (L2-resident for pass_v)

__device__ __forceinline__ u64 pack2(float lo, float hi) {
    u64 r; asm("mov.b64 %0, {%1, %2};" : "=l"(r) : "f"(lo), "f"(hi)); return r;
}
__device__ __forceinline__ void fma2(u64& d, u64 a, u64 b) {
    asm("fma.rn.f32x2 %0, %1, %2, %0;" : "+l"(d) : "l"(a), "l"(b));
}
__device__ __forceinline__ float2 unpack2(u64 v) {
    float2 f; asm("mov.b64 {%0, %1}, %2;" : "=f"(f.x), "=f"(f.y) : "l"(v)); return f;
}

// 13 symmetric 1D weights from row RR of the 2D kernel; center weight = 1
// (the zeroed 2D center tap is handled by subtracting src at the end).
__device__ __forceinline__ void load_weights(const float* __restrict__ k, u64* W2) {
#pragma unroll
    for (int j = 0; j < 12; ++j) {
        float w = __ldg(k + RR * TAPS + j);
        W2[j] = pack2(w, w);
    }
    W2[12] = pack2(1.0f, 1.0f);
}

// ---------------- Pass 1: horizontal. 16 adjacent x outputs per thread, -----
// scalar sliding window of 40 loads (L1-served gather), FFMA2 pairs.
__global__ void __launch_bounds__(256) pass_h_kernel(const float* __restrict__ src,
                                                     const float* __restrict__ k) {
    const int PER_ROW = (WW / 16) * CC;             // 672 threads per (b,y) row
    int tid = blockIdx.x * 256 + threadIdx.x;       // grid sized exactly

    int row = tid / PER_ROW;                        // b*HH + y
    int rem = tid - row * PER_ROW;
    int xg  = rem / CC;
    int c   = rem - xg * CC;
    int x0  = xg * 16;

    const float* rp = src   + (size_t)row * ROWF;
    __half*      op = g_tmp + (size_t)row * ROWF;
    int base = x0 * CC + c;

    u64 W2[13];
    load_weights(k, W2);

    float v[40];
    if (x0 >= RR && x0 + 27 < WW) {                 // interior: xin in range
#pragma unroll
        for (int s = 0; s < 40; ++s)
            v[s] = rp[base + (s - RR) * CC];
    } else {
#pragma unroll
        for (int s = 0; s < 40; ++s) {
            int xin = x0 - RR + s;
            v[s] = (xin >= 0 && xin < WW) ? rp[base + (s - RR) * CC] : 0.0f;
        }
    }

    // A[m] accumulates outputs (x0+2m, x0+2m+1), m = 0..7
    u64 A[8] = {0ull, 0ull, 0ull, 0ull, 0ull, 0ull, 0ull, 0ull};
#pragma unroll
    for (int i = 0; i < 39; ++i) {
        u64 P = pack2(v[i], v[i + 1]);
#pragma unroll
        for (int m = 0; m < 8; ++m) {
            int n = i - 2 * m;
            if (n >= 0 && n < TAPS)
                fma2(A[m], W2[n <= RR ? n : 24 - n], P);
        }
    }

#pragma unroll
    for (int m = 0; m < 8; ++m) {
        float2 o = unpack2(A[m]);
        op[base + (2 * m)     * CC] = __float2half_rn(o.x);
        op[base + (2 * m + 1) * CC] = __float2half_rn(o.y);
    }
}

// ---------------- Pass 2: vertical + subtract src (round-3, unchanged) -----
__global__ void __launch_bounds__(256) pass_v_kernel(const float* __restrict__ src,
                                                     const float* __restrict__ k,
                                                     float* __restrict__ dst) {
    const int PAIRS = ROWF / 2;                     // 5376 pairs per row
    const int PER_B = (HH / 8) * PAIRS;             // 344,064 threads per batch
    int tid = blockIdx.x * 256 + threadIdx.x;

    int b   = tid / PER_B;
    int rem = tid - b * PER_B;
    int yg  = rem / PAIRS;
    int fp  = rem - yg * PAIRS;
    int y0  = yg * 8;

    size_t off = (size_t)b * IMGF + 2 * (size_t)fp;
    const __half* tp = g_tmp + off;
    const float*  sp = src + off;
    float*        dp = dst + off;

    u64 W2[13];
    load_weights(k, W2);

    __half2 v[32];
    if (y0 >= RR && y0 + 19 < HH) {
#pragma unroll
        for (int s = 0; s < 32; ++s)
            v[s] = *(const __half2*)(tp + (size_t)(y0 - RR + s) * ROWF);
    } else {
        const __half2 z = __float2half2_rn(0.0f);
#pragma unroll
        for (int s = 0; s < 32; ++s) {
            int yin = y0 - RR + s;
            v[s] = (yin >= 0 && yin < HH)
                       ? *(const __half2*)(tp + (size_t)yin * ROWF)
                       : z;
        }
    }

    u64 A[8] = {0ull, 0ull, 0ull, 0ull, 0ull, 0ull, 0ull, 0ull};
#pragma unroll
    for (int s = 0; s < 32; ++s) {
        float2 f = __half22float2(v[s]);
        u64 P = pack2(f.x, f.y);
#pragma unroll
        for (int m = 0; m < 8; ++m) {
            int n = s - m;
            if (n >= 0 && n < TAPS)
                fma2(A[m], W2[n <= RR ? n : 24 - n], P);
        }
    }

#pragma unroll
    for (int m = 0; m < 8; ++m) {
        float2 o  = unpack2(A[m]);
        float2 s2 = *(const float2*)(sp + (size_t)(y0 + m) * ROWF);
        float2 r;
        r.x = o.x - s2.x;
        r.y = o.y - s2.y;
        *(float2*)(dp + (size_t)(y0 + m) * ROWF) = r;
    }
}

extern "C" void kernel_launch(void* const* d_in, const int* in_sizes, int n_in,
                              void* d_out, int out_size) {
    const float* src = (const float*)d_in[0];
    const float* k   = (const float*)d_in[1];
    float*       dst = (float*)d_out;

    int nthreads_h = BATCH * HH * (WW / 16) * CC;         // 1,376,256
    pass_h_kernel<<<nthreads_h / 256, 256>>>(src, k);

    int nthreads_v = BATCH * (HH / 8) * (ROWF / 2);       // 1,376,256
    pass_v_kernel<<<nthreads_v / 256, 256>>>(src, k, dst);
}